// round 14
// baseline (speedup 1.0000x reference)
#include <cuda_runtime.h>
#include <math.h>
#include <stdint.h>

#define NB     16
#define C_IN   128
#define HH_    64
#define WW_    64
#define HW     4096
#define OC_OFF 72
#define OG     4
#define CG     32
#define OUT_C  128
#define KK     9

typedef unsigned long long u64;

// ---- bf16 helpers (base sm_100 ISA) ----
__device__ __forceinline__ uint32_t bpack(float lo, float hi) {
    uint32_t r; asm("cvt.rn.bf16x2.f32 %0, %1, %2;" : "=r"(r) : "f"(hi), "f"(lo)); return r;
}
__device__ __forceinline__ void bsplit(float v0, float v1, uint32_t& ph, uint32_t& pl) {
    ph = bpack(v0, v1);
    float f0 = __uint_as_float(ph << 16);
    float f1 = __uint_as_float(ph & 0xffff0000u);
    pl = bpack(v0 - f0, v1 - f1);
}
__device__ __forceinline__ void mma_bf16(float* d, const uint32_t* a,
                                         uint32_t b0, uint32_t b1) {
    asm volatile(
        "mma.sync.aligned.m16n8k16.row.col.f32.bf16.bf16.f32 "
        "{%0,%1,%2,%3},{%4,%5,%6,%7},{%8,%9},{%0,%1,%2,%3};"
        : "+f"(d[0]), "+f"(d[1]), "+f"(d[2]), "+f"(d[3])
        : "r"(a[0]), "r"(a[1]), "r"(a[2]), "r"(a[3]), "r"(b0), "r"(b1));
}

// ---- fp16 helpers (offset conv 2-split) ----
__device__ __forceinline__ uint32_t hpack(float lo, float hi) {
    uint32_t r; asm("cvt.rn.f16x2.f32 %0, %1, %2;" : "=r"(r) : "f"(hi), "f"(lo)); return r;
}
__device__ __forceinline__ void hsplit(float v0, float v1, uint32_t& ph, uint32_t& pl) {
    ph = hpack(v0, v1);
    float f0, f1;
    asm("{.reg .f16 a,b;\n\t mov.b32 {a,b}, %2;\n\t cvt.f32.f16 %0, a;\n\t cvt.f32.f16 %1, b;}"
        : "=f"(f0), "=f"(f1) : "r"(ph));
    pl = hpack(v0 - f0, v1 - f1);
}
__device__ __forceinline__ void mma_f16(float* d, const uint32_t* a,
                                        uint32_t b0, uint32_t b1) {
    asm volatile(
        "mma.sync.aligned.m16n8k16.row.col.f32.f16.f16.f32 "
        "{%0,%1,%2,%3},{%4,%5,%6,%7},{%8,%9},{%0,%1,%2,%3};"
        : "+f"(d[0]), "+f"(d[1]), "+f"(d[2]), "+f"(d[3])
        : "r"(a[0]), "r"(a[1]), "r"(a[2]), "r"(a[3]), "r"(b0), "r"(b1));
}

// ================= static device scratch =================
__device__ float g_offset[NB * OC_OFF * HW];
__device__ float g_tmp   [NB * OUT_C  * HW];
// offset conv B fragments (fp16 hi only): [chunk8][s9][nt9][lane32] uint2{h0,h1}
__device__ uint2 g_wBf[8 * 9 * 9 * 32];
// deform  conv B fragments: [g4][tap9][ks2][nt4][lane32] uint4{h0,h1,l0,l1}
__device__ uint4 g_wDf[4 * 9 * 2 * 4 * 32];

// ================= kernel 0: weight prep =================
__global__ void prep_kernel(const float* __restrict__ w_off,
                            const float* __restrict__ w_dc) {
    int idx = blockIdx.x * blockDim.x + threadIdx.x;
    if (idx < 8 * 9 * 9 * 32) {
        int chunk = idx / (9 * 9 * 32);
        int rem   = idx % (9 * 9 * 32);
        int s     = rem / (9 * 32);
        int nt    = (rem / 32) % 9;
        int lane  = rem % 32;
        int g = lane >> 2, t = lane & 3;
        int oc = nt * 8 + g;
        float w00 = w_off[(oc * C_IN + chunk * 16 + 2 * t    ) * KK + s];
        float w01 = w_off[(oc * C_IN + chunk * 16 + 2 * t + 1) * KK + s];
        float w10 = w_off[(oc * C_IN + chunk * 16 + 2 * t + 8) * KK + s];
        float w11 = w_off[(oc * C_IN + chunk * 16 + 2 * t + 9) * KK + s];
        g_wBf[idx] = make_uint2(hpack(w00, w01), hpack(w10, w11));
    }
    if (idx < 4 * 9 * 2 * 4 * 32) {
        int g    = idx / (9 * 2 * 4 * 32);
        int rem  = idx % (9 * 2 * 4 * 32);
        int tap  = rem / (2 * 4 * 32);
        int ks   = (rem / (4 * 32)) % 2;
        int nt   = (rem / 32) % 4;
        int lane = rem % 32;
        int gg = lane >> 2, t = lane & 3;
        int oc = nt * 8 + gg;
        int k0 = ks * 16 + 2 * t;
        float w00 = w_dc[((g * CG + oc) * CG + k0    ) * KK + tap];
        float w01 = w_dc[((g * CG + oc) * CG + k0 + 1) * KK + tap];
        float w10 = w_dc[((g * CG + oc) * CG + k0 + 8) * KK + tap];
        float w11 = w_dc[((g * CG + oc) * CG + k0 + 9) * KK + tap];
        uint32_t h0, l0, h1, l1;
        bsplit(w00, w01, h0, l0);
        bsplit(w10, w11, h1, l1);
        g_wDf[idx] = make_uint4(h0, h1, l0, l1);
    }
}

// ================= kernel 1: offset conv via mma.sync fp16 2-split + cp.async =================
#define OFFB_THREADS 256
#define ST_CH  292
#define ST_ROW 72
#define STRIP_F (16 * ST_CH)
__global__ __launch_bounds__(OFFB_THREADS, 4)
void offset_conv_f16(const float* __restrict__ x,
                     const float* __restrict__ b_off) {
    __shared__ __align__(16) float strip[2][STRIP_F];

    const int h2 = blockIdx.x;
    const int n  = blockIdx.y;
    const int b  = n >> 3, d = n & 7;
    const int tid  = threadIdx.x;
    const int w    = tid >> 5;
    const int lane = tid & 31;
    const int g    = lane >> 2;
    const int t    = lane & 3;
    const int rowsel  = w >> 2;
    const int winbase = (w & 3) * 16;

    float acc[9][4];
#pragma unroll
    for (int nt = 0; nt < 9; nt++)
#pragma unroll
        for (int i = 0; i < 4; i++) acc[nt][i] = 0.f;

    const float* xn = x + (((size_t)b * C_IN) * 8 + d) * HW;
    const uint32_t sbase = (uint32_t)__cvta_generic_to_shared(&strip[0][0]);

    for (int i = tid; i < 2 * STRIP_F; i += OFFB_THREADS)
        (&strip[0][0])[i] = 0.f;
    __syncthreads();

    // async loader: cp.async.cg 16B; out-of-range rows never written (stay zero)
    auto loadStripAsync = [&](int buf, int chunk) {
#pragma unroll
        for (int j = 0; j < 4; j++) {
            int f4i = tid + OFFB_THREADS * j;
            int ch  = f4i >> 6;
            int rem = f4i & 63;
            int r   = rem >> 4;
            int q   = rem & 15;
            int hin = h2 * 2 - 1 + r;
            if (hin >= 0 && hin < HH_) {
                uint32_t dst = sbase + (uint32_t)(buf * STRIP_F + ch * ST_CH + r * ST_ROW + 4 + 4 * q) * 4u;
                const float* src = xn + (size_t)(chunk * 16 + ch) * (8 * HW) + hin * WW_ + 4 * q;
                asm volatile("cp.async.cg.shared.global [%0], [%1], 16;" :: "r"(dst), "l"(src));
            }
        }
        asm volatile("cp.async.commit_group;" ::: "memory");
    };

    loadStripAsync(0, 0);
    asm volatile("cp.async.wait_group 0;" ::: "memory");
    __syncthreads();

    for (int chunk = 0; chunk < 8; chunk++) {
        const int cur = chunk & 1;
        if (chunk < 7) loadStripAsync(cur ^ 1, chunk + 1);
        const float* S = strip[cur];
        const uint2* Bf = g_wBf + (size_t)chunk * (9 * 9 * 32) + lane;

#pragma unroll
        for (int s = 0; s < 9; s++) {
            const int ky = s / 3, kx = s - 3 * (s / 3);
            const int row  = rowsel + ky;
            const int colb = 3 + winbase + kx;
            const int b0i = (2 * t) * ST_CH + row * ST_ROW + colb;
            float v00 = S[b0i + g],                 v01 = S[b0i + ST_CH + g];
            float v10 = S[b0i + g + 8],             v11 = S[b0i + ST_CH + g + 8];
            float v20 = S[b0i + 8 * ST_CH + g],     v21 = S[b0i + 9 * ST_CH + g];
            float v30 = S[b0i + 8 * ST_CH + g + 8], v31 = S[b0i + 9 * ST_CH + g + 8];
            uint32_t ah[4], al[4];
            hsplit(v00, v01, ah[0], al[0]);
            hsplit(v10, v11, ah[1], al[1]);
            hsplit(v20, v21, ah[2], al[2]);
            hsplit(v30, v31, ah[3], al[3]);
#pragma unroll
            for (int nt = 0; nt < 9; nt++) {
                uint2 bf = __ldg(Bf + (s * 9 + nt) * 32);
                mma_f16(acc[nt], ah, bf.x, bf.y);   // hi*hi
                mma_f16(acc[nt], al, bf.x, bf.y);   // lo*hi  (w_lo dropped)
            }
        }
        if (chunk < 7) asm volatile("cp.async.wait_group 0;" ::: "memory");
        __syncthreads();
    }

    const int imgrow = h2 * 2 + rowsel;
    float* outp = g_offset + (size_t)n * (OC_OFF * HW) + imgrow * WW_ + winbase;
#pragma unroll
    for (int nt = 0; nt < 9; nt++) {
        int oc0 = nt * 8 + 2 * t;
        float bb0 = __ldg(b_off + oc0), bb1 = __ldg(b_off + oc0 + 1);
        outp[(size_t)oc0       * HW + g    ] = acc[nt][0] + bb0;
        outp[(size_t)(oc0 + 1) * HW + g    ] = acc[nt][1] + bb1;
        outp[(size_t)oc0       * HW + g + 8] = acc[nt][2] + bb0;
        outp[(size_t)(oc0 + 1) * HW + g + 8] = acc[nt][3] + bb1;
    }
}

// ================= kernel 2: deformable conv — NCHW sampling + bf16 mma (R11 exact) =================
#define DF_ROW 36    // u32 row stride per pixel: hi[16] @0, lo[16] @20
__global__ __launch_bounds__(128)
void deform_kernel(const float* __restrict__ x,
                   const float* __restrict__ b_dc) {
    __shared__ __align__(16) uint32_t samp[128 * DF_ROW];   // 18.4 KB
    __shared__ float offs[2 * KK][128];                     // 9 KB

    const int h2 = blockIdx.x;
    const int g  = blockIdx.y;
    const int n  = blockIdx.z;
    const int b  = n >> 3, d = n & 7;
    const int tid = threadIdx.x;
    const int w    = tid >> 5;
    const int lane = tid & 31;
    const int gl   = lane >> 2;
    const int t    = lane & 3;

    const int sp = tid;
    const int sh = h2 * 2 + (sp >> 6);
    const int sw = sp & 63;
    const float* xbase = x + (((size_t)b * C_IN + g * CG) * 8 + d) * HW;
    const float* offb  = g_offset + (size_t)n * (OC_OFF * HW)
                       + (size_t)(g * KK * 2) * HW + sh * WW_ + sw;

#pragma unroll
    for (int k = 0; k < 2 * KK; k++)
        offs[k][sp] = __ldg(offb + (size_t)k * HW);
    __syncthreads();

    float acc[2][4][4];
#pragma unroll
    for (int mt = 0; mt < 2; mt++)
#pragma unroll
        for (int nt = 0; nt < 4; nt++)
#pragma unroll
            for (int i = 0; i < 4; i++) acc[mt][nt][i] = 0.f;

    uint32_t* myrow = &samp[sp * DF_ROW];

#pragma unroll 1
    for (int k = 0; k < KK; k++) {
        int ky = k / 3, kx = k - 3 * (k / 3);
        float py = offs[2 * k][sp]     + (float)(sh + ky - 1);
        float px = offs[2 * k + 1][sp] + (float)(sw + kx - 1);
        float y0f = floorf(py), x0f = floorf(px);
        int   y0 = (int)y0f,   x0 = (int)x0f;
        float ly = py - y0f, lx = px - x0f;
        float hy = 1.f - ly, hx = 1.f - lx;
        bool vy0 = (y0 >= 0)  && (y0 < HH_);
        bool vy1 = (y0 >= -1) && (y0 < HH_ - 1);
        bool vx0 = (x0 >= 0)  && (x0 < WW_);
        bool vx1 = (x0 >= -1) && (x0 < WW_ - 1);
        int yc0 = min(max(y0, 0), HH_ - 1), yc1 = min(max(y0 + 1, 0), HH_ - 1);
        int xc0 = min(max(x0, 0), WW_ - 1), xc1 = min(max(x0 + 1, 0), WW_ - 1);
        float w00 = hy * hx * (float)(vy0 && vx0);
        float w01 = hy * lx * (float)(vy0 && vx1);
        float w10 = ly * hx * (float)(vy1 && vx0);
        float w11 = ly * lx * (float)(vy1 && vx1);
        int i00 = yc0 * WW_ + xc0, i01 = yc0 * WW_ + xc1;
        int i10 = yc1 * WW_ + xc0, i11 = yc1 * WW_ + xc1;

        uint32_t hi[16], lo[16];
#pragma unroll
        for (int cp = 0; cp < 16; cp++) {
            const float* xp0 = xbase + (size_t)(2 * cp)     * (8 * HW);
            const float* xp1 = xbase + (size_t)(2 * cp + 1) * (8 * HW);
            float v0 = w00 * __ldg(xp0 + i00) + w01 * __ldg(xp0 + i01)
                     + w10 * __ldg(xp0 + i10) + w11 * __ldg(xp0 + i11);
            float v1 = w00 * __ldg(xp1 + i00) + w01 * __ldg(xp1 + i01)
                     + w10 * __ldg(xp1 + i10) + w11 * __ldg(xp1 + i11);
            bsplit(v0, v1, hi[cp], lo[cp]);
        }
        reinterpret_cast<uint4*>(myrow)[0] = make_uint4(hi[0], hi[1], hi[2], hi[3]);
        reinterpret_cast<uint4*>(myrow)[1] = make_uint4(hi[4], hi[5], hi[6], hi[7]);
        reinterpret_cast<uint4*>(myrow)[2] = make_uint4(hi[8], hi[9], hi[10], hi[11]);
        reinterpret_cast<uint4*>(myrow)[3] = make_uint4(hi[12], hi[13], hi[14], hi[15]);
        reinterpret_cast<uint4*>(myrow + 20)[0] = make_uint4(lo[0], lo[1], lo[2], lo[3]);
        reinterpret_cast<uint4*>(myrow + 20)[1] = make_uint4(lo[4], lo[5], lo[6], lo[7]);
        reinterpret_cast<uint4*>(myrow + 20)[2] = make_uint4(lo[8], lo[9], lo[10], lo[11]);
        reinterpret_cast<uint4*>(myrow + 20)[3] = make_uint4(lo[12], lo[13], lo[14], lo[15]);
        __syncwarp();

#pragma unroll
        for (int ks = 0; ks < 2; ks++) {
            uint32_t ah[2][4], al[2][4];
#pragma unroll
            for (int mt = 0; mt < 2; mt++) {
                int r0 = (w * 32 + mt * 16 + gl) * DF_ROW + ks * 8;
                int r1 = r0 + 8 * DF_ROW;
                ah[mt][0] = samp[r0 + t];
                ah[mt][1] = samp[r1 + t];
                ah[mt][2] = samp[r0 + t + 4];
                ah[mt][3] = samp[r1 + t + 4];
                al[mt][0] = samp[r0 + 20 + t];
                al[mt][1] = samp[r1 + 20 + t];
                al[mt][2] = samp[r0 + 20 + t + 4];
                al[mt][3] = samp[r1 + 20 + t + 4];
            }
            const uint4* Bp = g_wDf + (((size_t)(g * 9 + k) * 2 + ks) * 4) * 32 + lane;
#pragma unroll
            for (int nt = 0; nt < 4; nt++) {
                uint4 bf = __ldg(Bp + nt * 32);
#pragma unroll
                for (int mt = 0; mt < 2; mt++) {
                    mma_bf16(acc[mt][nt], ah[mt], bf.x, bf.y);
                    mma_bf16(acc[mt][nt], al[mt], bf.x, bf.y);
                    mma_bf16(acc[mt][nt], ah[mt], bf.z, bf.w);
                }
            }
        }
        __syncwarp();
    }

    float* outp = g_tmp + ((size_t)n * OUT_C + g * CG) * HW + h2 * 128;
#pragma unroll
    for (int mt = 0; mt < 2; mt++) {
        int px0 = w * 32 + mt * 16 + gl;
#pragma unroll
        for (int nt = 0; nt < 4; nt++) {
            int oc0 = nt * 8 + 2 * t;
            float bb0 = __ldg(b_dc + g * CG + oc0);
            float bb1 = __ldg(b_dc + g * CG + oc0 + 1);
            outp[(size_t)oc0       * HW + px0    ] = acc[mt][nt][0] + bb0;
            outp[(size_t)(oc0 + 1) * HW + px0    ] = acc[mt][nt][1] + bb1;
            outp[(size_t)oc0       * HW + px0 + 8] = acc[mt][nt][2] + bb0;
            outp[(size_t)(oc0 + 1) * HW + px0 + 8] = acc[mt][nt][3] + bb1;
        }
    }
}

// ================= kernel 3: instance norm + GELU + transpose =================
__global__ __launch_bounds__(256)
void finalize_kernel(float* __restrict__ out) {
    const int c = blockIdx.x;
    const int n = blockIdx.y;
    const int b = n >> 3, d = n & 7;
    const int tid = threadIdx.x;

    const float* tp = g_tmp + ((size_t)n * OUT_C + c) * HW;
    float v[16];
    float s = 0.f, ss = 0.f;
#pragma unroll
    for (int i = 0; i < 16; i++) {
        float t = tp[tid + 256 * i];
        v[i] = t; s += t; ss += t * t;
    }
#pragma unroll
    for (int o = 16; o > 0; o >>= 1) {
        s  += __shfl_down_sync(0xffffffffu, s,  o);
        ss += __shfl_down_sync(0xffffffffu, ss, o);
    }
    __shared__ float s1[8], s2[8];
    __shared__ float mu_s, inv_s;
    int wid = tid >> 5, lane = tid & 31;
    if (lane == 0) { s1[wid] = s; s2[wid] = ss; }
    __syncthreads();
    if (tid == 0) {
        float ts = 0.f, tss = 0.f;
#pragma unroll
        for (int i = 0; i < 8; i++) { ts += s1[i]; tss += s2[i]; }
        float mu  = ts * (1.f / 4096.f);
        float var = tss * (1.f / 4096.f) - mu * mu;
        mu_s  = mu;
        inv_s = rsqrtf(var + 1e-5f);
    }
    __syncthreads();
    float mu = mu_s, inv = inv_s;

    float* op = out + (((size_t)b * OUT_C + c) * 8 + d) * HW;
#pragma unroll
    for (int i = 0; i < 16; i++) {
        float t = (v[i] - mu) * inv;
        op[tid + 256 * i] = 0.5f * t * (1.f + erff(t * 0.70710678118654752f));
    }
}

// ================= launcher: monolithic serial chain =================
extern "C" void kernel_launch(void* const* d_in, const int* in_sizes, int n_in,
                              void* d_out, int out_size) {
    (void)in_sizes; (void)n_in; (void)out_size;
    const float* x     = (const float*)d_in[0];
    const float* w_off = (const float*)d_in[1];
    const float* b_off = (const float*)d_in[2];
    const float* w_dc  = (const float*)d_in[3];
    const float* b_dc  = (const float*)d_in[4];
    float* out = (float*)d_out;

    prep_kernel<<<(8 * 9 * 9 * 32 + 255) / 256, 256>>>(w_off, w_dc);

    dim3 gco(32, NB);
    offset_conv_f16<<<gco, OFFB_THREADS>>>(x, b_off);

    dim3 gdf(32, OG, NB);
    deform_kernel<<<gdf, 128>>>(x, b_dc);

    dim3 gfn(OUT_C, NB);
    finalize_kernel<<<gfn, 256>>>(out);
}

// round 15
// speedup vs baseline: 1.3107x; 1.3107x over previous
#include <cuda_runtime.h>
#include <math.h>
#include <stdint.h>

#define NB     16
#define C_IN   128
#define HH_    64
#define WW_    64
#define HW     4096
#define OC_OFF 72
#define OG     4
#define CG     32
#define OUT_C  128
#define KK     9

typedef unsigned long long u64;

// ---- bf16 helpers (base sm_100 ISA) ----
__device__ __forceinline__ uint32_t bpack(float lo, float hi) {
    uint32_t r; asm("cvt.rn.bf16x2.f32 %0, %1, %2;" : "=r"(r) : "f"(hi), "f"(lo)); return r;
}
__device__ __forceinline__ void bsplit(float v0, float v1, uint32_t& ph, uint32_t& pl) {
    ph = bpack(v0, v1);
    float f0 = __uint_as_float(ph << 16);
    float f1 = __uint_as_float(ph & 0xffff0000u);
    pl = bpack(v0 - f0, v1 - f1);
}
__device__ __forceinline__ void mma_bf16(float* d, const uint32_t* a,
                                         uint32_t b0, uint32_t b1) {
    asm volatile(
        "mma.sync.aligned.m16n8k16.row.col.f32.bf16.bf16.f32 "
        "{%0,%1,%2,%3},{%4,%5,%6,%7},{%8,%9},{%0,%1,%2,%3};"
        : "+f"(d[0]), "+f"(d[1]), "+f"(d[2]), "+f"(d[3])
        : "r"(a[0]), "r"(a[1]), "r"(a[2]), "r"(a[3]), "r"(b0), "r"(b1));
}

// ---- fp16 helpers ----
__device__ __forceinline__ uint32_t hpack(float lo, float hi) {
    uint32_t r; asm("cvt.rn.f16x2.f32 %0, %1, %2;" : "=r"(r) : "f"(hi), "f"(lo)); return r;
}
__device__ __forceinline__ void h2f(uint32_t p, float& lo, float& hi) {
    asm("{.reg .f16 a,b;\n\t mov.b32 {a,b}, %2;\n\t cvt.f32.f16 %0, a;\n\t cvt.f32.f16 %1, b;}"
        : "=f"(lo), "=f"(hi) : "r"(p));
}
__device__ __forceinline__ void hsplit(float v0, float v1, uint32_t& ph, uint32_t& pl) {
    ph = hpack(v0, v1);
    float f0, f1;
    h2f(ph, f0, f1);
    pl = hpack(v0 - f0, v1 - f1);
}
__device__ __forceinline__ void mma_f16(float* d, const uint32_t* a,
                                        uint32_t b0, uint32_t b1) {
    asm volatile(
        "mma.sync.aligned.m16n8k16.row.col.f32.f16.f16.f32 "
        "{%0,%1,%2,%3},{%4,%5,%6,%7},{%8,%9},{%0,%1,%2,%3};"
        : "+f"(d[0]), "+f"(d[1]), "+f"(d[2]), "+f"(d[3])
        : "r"(a[0]), "r"(a[1]), "r"(a[2]), "r"(a[3]), "r"(b0), "r"(b1));
}

// ================= static device scratch =================
__device__ float    g_offset[NB * OC_OFF * HW];
__device__ float    g_tmp   [NB * OUT_C  * HW];
__device__ uint32_t g_xh    [NB * 64 * HW];              // fp16x2 channel pairs, 16.7MB
// offset conv B fragments (fp16 hi only): [chunk8][s9][nt9][lane32] uint2{h0,h1}
__device__ uint2 g_wBf[8 * 9 * 9 * 32];
// deform  conv B fragments: [g4][tap9][ks2][nt4][lane32] uint4{h0,h1,l0,l1}
__device__ uint4 g_wDf[4 * 9 * 2 * 4 * 32];

// ================= kernel 0: weight prep =================
__global__ void prep_kernel(const float* __restrict__ w_off,
                            const float* __restrict__ w_dc) {
    int idx = blockIdx.x * blockDim.x + threadIdx.x;
    if (idx < 8 * 9 * 9 * 32) {
        int chunk = idx / (9 * 9 * 32);
        int rem   = idx % (9 * 9 * 32);
        int s     = rem / (9 * 32);
        int nt    = (rem / 32) % 9;
        int lane  = rem % 32;
        int g = lane >> 2, t = lane & 3;
        int oc = nt * 8 + g;
        float w00 = w_off[(oc * C_IN + chunk * 16 + 2 * t    ) * KK + s];
        float w01 = w_off[(oc * C_IN + chunk * 16 + 2 * t + 1) * KK + s];
        float w10 = w_off[(oc * C_IN + chunk * 16 + 2 * t + 8) * KK + s];
        float w11 = w_off[(oc * C_IN + chunk * 16 + 2 * t + 9) * KK + s];
        g_wBf[idx] = make_uint2(hpack(w00, w01), hpack(w10, w11));
    }
    if (idx < 4 * 9 * 2 * 4 * 32) {
        int g    = idx / (9 * 2 * 4 * 32);
        int rem  = idx % (9 * 2 * 4 * 32);
        int tap  = rem / (2 * 4 * 32);
        int ks   = (rem / (4 * 32)) % 2;
        int nt   = (rem / 32) % 4;
        int lane = rem % 32;
        int gg = lane >> 2, t = lane & 3;
        int oc = nt * 8 + gg;
        int k0 = ks * 16 + 2 * t;
        float w00 = w_dc[((g * CG + oc) * CG + k0    ) * KK + tap];
        float w01 = w_dc[((g * CG + oc) * CG + k0 + 1) * KK + tap];
        float w10 = w_dc[((g * CG + oc) * CG + k0 + 8) * KK + tap];
        float w11 = w_dc[((g * CG + oc) * CG + k0 + 9) * KK + tap];
        uint32_t h0, l0, h1, l1;
        bsplit(w00, w01, h0, l0);
        bsplit(w10, w11, h1, l1);
        g_wDf[idx] = make_uint4(h0, h1, l0, l1);
    }
}

// ================= kernel 0b: x -> fp16x2 channel-pair copy =================
// g_xh[n][cp][px] = {fp16(x[2cp]), fp16(x[2cp+1])} at px. Both sides coalesced.
__global__ __launch_bounds__(256)
void xhalf_kernel(const float* __restrict__ x) {
    const int cp = blockIdx.x;          // 0..63 (global channel pair)
    const int n  = blockIdx.y;          // 0..15
    const int b  = n >> 3, d = n & 7;
    const int tid = threadIdx.x;
    const float* x0 = x + (((size_t)(b * C_IN + 2 * cp)) * 8 + d) * HW;
    const float* x1 = x0 + 8 * HW;
    uint32_t* o = g_xh + ((size_t)(n * 64 + cp)) * HW;
#pragma unroll
    for (int i = 0; i < 16; i++) {
        int px = tid + 256 * i;
        o[px] = hpack(__ldg(x0 + px), __ldg(x1 + px));
    }
}

// ================= kernel 1: offset conv via mma.sync fp16 2-split (R11 exact) =================
#define OFFB_THREADS 256
#define ST_CH  292
#define ST_ROW 72
#define STRIP_F (16 * ST_CH)
__global__ __launch_bounds__(OFFB_THREADS, 3)
void offset_conv_f16(const float* __restrict__ x,
                     const float* __restrict__ b_off) {
    __shared__ __align__(16) float strip[2][STRIP_F];

    const int h2 = blockIdx.x;
    const int n  = blockIdx.y;
    const int b  = n >> 3, d = n & 7;
    const int tid  = threadIdx.x;
    const int w    = tid >> 5;
    const int lane = tid & 31;
    const int g    = lane >> 2;
    const int t    = lane & 3;
    const int rowsel  = w >> 2;
    const int winbase = (w & 3) * 16;

    float acc[9][4];
#pragma unroll
    for (int nt = 0; nt < 9; nt++)
#pragma unroll
        for (int i = 0; i < 4; i++) acc[nt][i] = 0.f;

    const float* xn = x + (((size_t)b * C_IN) * 8 + d) * HW;

    for (int i = tid; i < 2 * STRIP_F; i += OFFB_THREADS)
        (&strip[0][0])[i] = 0.f;
    __syncthreads();

    auto loadStrip = [&](int buf, int chunk) {
#pragma unroll
        for (int j = 0; j < 4; j++) {
            int f4i = tid + OFFB_THREADS * j;
            int ch  = f4i >> 6;
            int rem = f4i & 63;
            int r   = rem >> 4;
            int q   = rem & 15;
            int hin = h2 * 2 - 1 + r;
            if (hin >= 0 && hin < HH_) {
                float4 v = __ldg(reinterpret_cast<const float4*>(
                    xn + (size_t)(chunk * 16 + ch) * (8 * HW) + hin * WW_ + 4 * q));
                *reinterpret_cast<float4*>(&strip[buf][ch * ST_CH + r * ST_ROW + 4 + 4 * q]) = v;
            }
        }
    };

    loadStrip(0, 0);
    __syncthreads();

    for (int chunk = 0; chunk < 8; chunk++) {
        const int cur = chunk & 1;
        if (chunk < 7) loadStrip(cur ^ 1, chunk + 1);
        const float* S = strip[cur];
        const uint2* Bf = g_wBf + (size_t)chunk * (9 * 9 * 32) + lane;

#pragma unroll
        for (int s = 0; s < 9; s++) {
            const int ky = s / 3, kx = s - 3 * (s / 3);
            const int row  = rowsel + ky;
            const int colb = 3 + winbase + kx;
            const int b0i = (2 * t) * ST_CH + row * ST_ROW + colb;
            float v00 = S[b0i + g],                 v01 = S[b0i + ST_CH + g];
            float v10 = S[b0i + g + 8],             v11 = S[b0i + ST_CH + g + 8];
            float v20 = S[b0i + 8 * ST_CH + g],     v21 = S[b0i + 9 * ST_CH + g];
            float v30 = S[b0i + 8 * ST_CH + g + 8], v31 = S[b0i + 9 * ST_CH + g + 8];
            uint32_t ah[4], al[4];
            hsplit(v00, v01, ah[0], al[0]);
            hsplit(v10, v11, ah[1], al[1]);
            hsplit(v20, v21, ah[2], al[2]);
            hsplit(v30, v31, ah[3], al[3]);
#pragma unroll
            for (int nt = 0; nt < 9; nt++) {
                uint2 bf = __ldg(Bf + (s * 9 + nt) * 32);
                mma_f16(acc[nt], ah, bf.x, bf.y);   // hi*hi
                mma_f16(acc[nt], al, bf.x, bf.y);   // lo*hi  (w_lo dropped)
            }
        }
        __syncthreads();
    }

    const int imgrow = h2 * 2 + rowsel;
    float* outp = g_offset + (size_t)n * (OC_OFF * HW) + imgrow * WW_ + winbase;
#pragma unroll
    for (int nt = 0; nt < 9; nt++) {
        int oc0 = nt * 8 + 2 * t;
        float bb0 = __ldg(b_off + oc0), bb1 = __ldg(b_off + oc0 + 1);
        outp[(size_t)oc0       * HW + g    ] = acc[nt][0] + bb0;
        outp[(size_t)(oc0 + 1) * HW + g    ] = acc[nt][1] + bb1;
        outp[(size_t)oc0       * HW + g + 8] = acc[nt][2] + bb0;
        outp[(size_t)(oc0 + 1) * HW + g + 8] = acc[nt][3] + bb1;
    }
}

// ================= kernel 2: deformable conv — fp16x2-pair sampling + bf16 mma =================
// R11 structure; sampling loads halved via g_xh (4B granule keeps coalescing).
#define DF_ROW 36    // u32 row stride per pixel: hi[16] @0, lo[16] @20
__global__ __launch_bounds__(128)
void deform_kernel(const float* __restrict__ b_dc) {
    __shared__ __align__(16) uint32_t samp[128 * DF_ROW];   // 18.4 KB
    __shared__ float offs[2 * KK][128];                     // 9 KB

    const int h2 = blockIdx.x;
    const int g  = blockIdx.y;
    const int n  = blockIdx.z;
    const int tid = threadIdx.x;
    const int w    = tid >> 5;
    const int lane = tid & 31;
    const int gl   = lane >> 2;
    const int t    = lane & 3;

    const int sp = tid;
    const int sh = h2 * 2 + (sp >> 6);
    const int sw = sp & 63;
    const uint32_t* xh  = g_xh + ((size_t)(n * 64 + g * 16)) * HW;
    const float*   offb = g_offset + (size_t)n * (OC_OFF * HW)
                        + (size_t)(g * KK * 2) * HW + sh * WW_ + sw;

#pragma unroll
    for (int k = 0; k < 2 * KK; k++)
        offs[k][sp] = __ldg(offb + (size_t)k * HW);
    __syncthreads();

    float acc[2][4][4];
#pragma unroll
    for (int mt = 0; mt < 2; mt++)
#pragma unroll
        for (int nt = 0; nt < 4; nt++)
#pragma unroll
            for (int i = 0; i < 4; i++) acc[mt][nt][i] = 0.f;

    uint32_t* myrow = &samp[sp * DF_ROW];

#pragma unroll 1
    for (int k = 0; k < KK; k++) {
        int ky = k / 3, kx = k - 3 * (k / 3);
        float py = offs[2 * k][sp]     + (float)(sh + ky - 1);
        float px = offs[2 * k + 1][sp] + (float)(sw + kx - 1);
        float y0f = floorf(py), x0f = floorf(px);
        int   y0 = (int)y0f,   x0 = (int)x0f;
        float ly = py - y0f, lx = px - x0f;
        float hy = 1.f - ly, hx = 1.f - lx;
        bool vy0 = (y0 >= 0)  && (y0 < HH_);
        bool vy1 = (y0 >= -1) && (y0 < HH_ - 1);
        bool vx0 = (x0 >= 0)  && (x0 < WW_);
        bool vx1 = (x0 >= -1) && (x0 < WW_ - 1);
        int yc0 = min(max(y0, 0), HH_ - 1), yc1 = min(max(y0 + 1, 0), HH_ - 1);
        int xc0 = min(max(x0, 0), WW_ - 1), xc1 = min(max(x0 + 1, 0), WW_ - 1);
        float w00 = hy * hx * (float)(vy0 && vx0);
        float w01 = hy * lx * (float)(vy0 && vx1);
        float w10 = ly * hx * (float)(vy1 && vx0);
        float w11 = ly * lx * (float)(vy1 && vx1);
        int i00 = yc0 * WW_ + xc0, i01 = yc0 * WW_ + xc1;
        int i10 = yc1 * WW_ + xc0, i11 = yc1 * WW_ + xc1;

        uint32_t hi[16], lo[16];
#pragma unroll
        for (int cp = 0; cp < 16; cp++) {
            const uint32_t* xc = xh + (size_t)cp * HW;
            uint32_t q00 = __ldg(xc + i00);
            uint32_t q01 = __ldg(xc + i01);
            uint32_t q10 = __ldg(xc + i10);
            uint32_t q11 = __ldg(xc + i11);
            float a0, a1, b0, b1, c0, c1, d0, d1;
            h2f(q00, a0, a1);
            h2f(q01, b0, b1);
            h2f(q10, c0, c1);
            h2f(q11, d0, d1);
            float v0 = fmaf(w00, a0, fmaf(w01, b0, fmaf(w10, c0, w11 * d0)));
            float v1 = fmaf(w00, a1, fmaf(w01, b1, fmaf(w10, c1, w11 * d1)));
            bsplit(v0, v1, hi[cp], lo[cp]);
        }
        reinterpret_cast<uint4*>(myrow)[0] = make_uint4(hi[0], hi[1], hi[2], hi[3]);
        reinterpret_cast<uint4*>(myrow)[1] = make_uint4(hi[4], hi[5], hi[6], hi[7]);
        reinterpret_cast<uint4*>(myrow)[2] = make_uint4(hi[8], hi[9], hi[10], hi[11]);
        reinterpret_cast<uint4*>(myrow)[3] = make_uint4(hi[12], hi[13], hi[14], hi[15]);
        reinterpret_cast<uint4*>(myrow + 20)[0] = make_uint4(lo[0], lo[1], lo[2], lo[3]);
        reinterpret_cast<uint4*>(myrow + 20)[1] = make_uint4(lo[4], lo[5], lo[6], lo[7]);
        reinterpret_cast<uint4*>(myrow + 20)[2] = make_uint4(lo[8], lo[9], lo[10], lo[11]);
        reinterpret_cast<uint4*>(myrow + 20)[3] = make_uint4(lo[12], lo[13], lo[14], lo[15]);
        __syncwarp();

#pragma unroll
        for (int ks = 0; ks < 2; ks++) {
            uint32_t ah[2][4], al[2][4];
#pragma unroll
            for (int mt = 0; mt < 2; mt++) {
                int r0 = (w * 32 + mt * 16 + gl) * DF_ROW + ks * 8;
                int r1 = r0 + 8 * DF_ROW;
                ah[mt][0] = samp[r0 + t];
                ah[mt][1] = samp[r1 + t];
                ah[mt][2] = samp[r0 + t + 4];
                ah[mt][3] = samp[r1 + t + 4];
                al[mt][0] = samp[r0 + 20 + t];
                al[mt][1] = samp[r1 + 20 + t];
                al[mt][2] = samp[r0 + 20 + t + 4];
                al[mt][3] = samp[r1 + 20 + t + 4];
            }
            const uint4* Bp = g_wDf + (((size_t)(g * 9 + k) * 2 + ks) * 4) * 32 + lane;
#pragma unroll
            for (int nt = 0; nt < 4; nt++) {
                uint4 bf = __ldg(Bp + nt * 32);
#pragma unroll
                for (int mt = 0; mt < 2; mt++) {
                    mma_bf16(acc[mt][nt], ah[mt], bf.x, bf.y);
                    mma_bf16(acc[mt][nt], al[mt], bf.x, bf.y);
                    mma_bf16(acc[mt][nt], ah[mt], bf.z, bf.w);
                }
            }
        }
        __syncwarp();
    }

    float* outp = g_tmp + ((size_t)n * OUT_C + g * CG) * HW + h2 * 128;
#pragma unroll
    for (int mt = 0; mt < 2; mt++) {
        int px0 = w * 32 + mt * 16 + gl;
#pragma unroll
        for (int nt = 0; nt < 4; nt++) {
            int oc0 = nt * 8 + 2 * t;
            float bb0 = __ldg(b_dc + g * CG + oc0);
            float bb1 = __ldg(b_dc + g * CG + oc0 + 1);
            outp[(size_t)oc0       * HW + px0    ] = acc[mt][nt][0] + bb0;
            outp[(size_t)(oc0 + 1) * HW + px0    ] = acc[mt][nt][1] + bb1;
            outp[(size_t)oc0       * HW + px0 + 8] = acc[mt][nt][2] + bb0;
            outp[(size_t)(oc0 + 1) * HW + px0 + 8] = acc[mt][nt][3] + bb1;
        }
    }
}

// ================= kernel 3: instance norm + GELU + transpose =================
__global__ __launch_bounds__(256)
void finalize_kernel(float* __restrict__ out) {
    const int c = blockIdx.x;
    const int n = blockIdx.y;
    const int b = n >> 3, d = n & 7;
    const int tid = threadIdx.x;

    const float* tp = g_tmp + ((size_t)n * OUT_C + c) * HW;
    float v[16];
    float s = 0.f, ss = 0.f;
#pragma unroll
    for (int i = 0; i < 16; i++) {
        float t = tp[tid + 256 * i];
        v[i] = t; s += t; ss += t * t;
    }
#pragma unroll
    for (int o = 16; o > 0; o >>= 1) {
        s  += __shfl_down_sync(0xffffffffu, s,  o);
        ss += __shfl_down_sync(0xffffffffu, ss, o);
    }
    __shared__ float s1[8], s2[8];
    __shared__ float mu_s, inv_s;
    int wid = tid >> 5, lane = tid & 31;
    if (lane == 0) { s1[wid] = s; s2[wid] = ss; }
    __syncthreads();
    if (tid == 0) {
        float ts = 0.f, tss = 0.f;
#pragma unroll
        for (int i = 0; i < 8; i++) { ts += s1[i]; tss += s2[i]; }
        float mu  = ts * (1.f / 4096.f);
        float var = tss * (1.f / 4096.f) - mu * mu;
        mu_s  = mu;
        inv_s = rsqrtf(var + 1e-5f);
    }
    __syncthreads();
    float mu = mu_s, inv = inv_s;

    float* op = out + (((size_t)b * OUT_C + c) * 8 + d) * HW;
#pragma unroll
    for (int i = 0; i < 16; i++) {
        float t = (v[i] - mu) * inv;
        op[tid + 256 * i] = 0.5f * t * (1.f + erff(t * 0.70710678118654752f));
    }
}

// ================= launcher: monolithic serial chain =================
extern "C" void kernel_launch(void* const* d_in, const int* in_sizes, int n_in,
                              void* d_out, int out_size) {
    (void)in_sizes; (void)n_in; (void)out_size;
    const float* x     = (const float*)d_in[0];
    const float* w_off = (const float*)d_in[1];
    const float* b_off = (const float*)d_in[2];
    const float* w_dc  = (const float*)d_in[3];
    const float* b_dc  = (const float*)d_in[4];
    float* out = (float*)d_out;

    prep_kernel<<<(8 * 9 * 9 * 32 + 255) / 256, 256>>>(w_off, w_dc);

    dim3 gxh(64, NB);
    xhalf_kernel<<<gxh, 256>>>(x);

    dim3 gco(32, NB);
    offset_conv_f16<<<gco, OFFB_THREADS>>>(x, b_off);

    dim3 gdf(32, OG, NB);
    deform_kernel<<<gdf, 128>>>(b_dc);

    dim3 gfn(OUT_C, NB);
    finalize_kernel<<<gfn, 256>>>(out);
}

// round 16
// speedup vs baseline: 1.4671x; 1.1194x over previous
#include <cuda_runtime.h>
#include <math.h>
#include <stdint.h>

#define NB     16
#define C_IN   128
#define HH_    64
#define WW_    64
#define HW     4096
#define OC_OFF 72
#define OG     4
#define CG     32
#define OUT_C  128
#define KK     9

typedef unsigned long long u64;

// ---- bf16 helpers (base sm_100 ISA) ----
__device__ __forceinline__ uint32_t bpack(float lo, float hi) {
    uint32_t r; asm("cvt.rn.bf16x2.f32 %0, %1, %2;" : "=r"(r) : "f"(hi), "f"(lo)); return r;
}
// ---- fp16 helpers ----
__device__ __forceinline__ uint32_t hpack(float lo, float hi) {
    uint32_t r; asm("cvt.rn.f16x2.f32 %0, %1, %2;" : "=r"(r) : "f"(hi), "f"(lo)); return r;
}
__device__ __forceinline__ void h2f(uint32_t p, float& lo, float& hi) {
    asm("{.reg .f16 a,b;\n\t mov.b32 {a,b}, %2;\n\t cvt.f32.f16 %0, a;\n\t cvt.f32.f16 %1, b;}"
        : "=f"(lo), "=f"(hi) : "r"(p));
}
__device__ __forceinline__ void hsplit(float v0, float v1, uint32_t& ph, uint32_t& pl) {
    ph = hpack(v0, v1);
    float f0, f1;
    h2f(ph, f0, f1);
    pl = hpack(v0 - f0, v1 - f1);
}
__device__ __forceinline__ void mma_f16(float* d, const uint32_t* a,
                                        uint32_t b0, uint32_t b1) {
    asm volatile(
        "mma.sync.aligned.m16n8k16.row.col.f32.f16.f16.f32 "
        "{%0,%1,%2,%3},{%4,%5,%6,%7},{%8,%9},{%0,%1,%2,%3};"
        : "+f"(d[0]), "+f"(d[1]), "+f"(d[2]), "+f"(d[3])
        : "r"(a[0]), "r"(a[1]), "r"(a[2]), "r"(a[3]), "r"(b0), "r"(b1));
}

// ================= static device scratch =================
__device__ float    g_offset[NB * OC_OFF * HW];
__device__ float    g_tmp   [NB * OUT_C  * HW];
__device__ uint32_t g_xh    [NB * 64 * HW];              // fp16x2 channel pairs, 16.7MB
// offset conv B fragments (fp16 hi only): [chunk8][s9][nt9][lane32] uint2{h0,h1}
__device__ uint2 g_wBf[8 * 9 * 9 * 32];
// deform  conv B fragments (fp16 hi/lo): [g4][tap9][ks2][nt4][lane32] uint4{h0,h1,l0,l1}
__device__ uint4 g_wDf[4 * 9 * 2 * 4 * 32];

// ================= kernel 0: weight prep =================
__global__ void prep_kernel(const float* __restrict__ w_off,
                            const float* __restrict__ w_dc) {
    int idx = blockIdx.x * blockDim.x + threadIdx.x;
    if (idx < 8 * 9 * 9 * 32) {
        int chunk = idx / (9 * 9 * 32);
        int rem   = idx % (9 * 9 * 32);
        int s     = rem / (9 * 32);
        int nt    = (rem / 32) % 9;
        int lane  = rem % 32;
        int g = lane >> 2, t = lane & 3;
        int oc = nt * 8 + g;
        float w00 = w_off[(oc * C_IN + chunk * 16 + 2 * t    ) * KK + s];
        float w01 = w_off[(oc * C_IN + chunk * 16 + 2 * t + 1) * KK + s];
        float w10 = w_off[(oc * C_IN + chunk * 16 + 2 * t + 8) * KK + s];
        float w11 = w_off[(oc * C_IN + chunk * 16 + 2 * t + 9) * KK + s];
        g_wBf[idx] = make_uint2(hpack(w00, w01), hpack(w10, w11));
    }
    if (idx < 4 * 9 * 2 * 4 * 32) {
        int g    = idx / (9 * 2 * 4 * 32);
        int rem  = idx % (9 * 2 * 4 * 32);
        int tap  = rem / (2 * 4 * 32);
        int ks   = (rem / (4 * 32)) % 2;
        int nt   = (rem / 32) % 4;
        int lane = rem % 32;
        int gg = lane >> 2, t = lane & 3;
        int oc = nt * 8 + gg;
        int k0 = ks * 16 + 2 * t;
        float w00 = w_dc[((g * CG + oc) * CG + k0    ) * KK + tap];
        float w01 = w_dc[((g * CG + oc) * CG + k0 + 1) * KK + tap];
        float w10 = w_dc[((g * CG + oc) * CG + k0 + 8) * KK + tap];
        float w11 = w_dc[((g * CG + oc) * CG + k0 + 9) * KK + tap];
        uint32_t h0, l0, h1, l1;
        hsplit(w00, w01, h0, l0);
        hsplit(w10, w11, h1, l1);
        g_wDf[idx] = make_uint4(h0, h1, l0, l1);
    }
}

// ================= kernel 0b: x -> fp16x2 channel-pair copy =================
__global__ __launch_bounds__(256)
void xhalf_kernel(const float* __restrict__ x) {
    const int cp = blockIdx.x;          // 0..63
    const int n  = blockIdx.y;          // 0..15
    const int b  = n >> 3, d = n & 7;
    const int tid = threadIdx.x;
    const float* x0 = x + (((size_t)(b * C_IN + 2 * cp)) * 8 + d) * HW;
    const float* x1 = x0 + 8 * HW;
    uint32_t* o = g_xh + ((size_t)(n * 64 + cp)) * HW;
#pragma unroll
    for (int i = 0; i < 16; i++) {
        int px = tid + 256 * i;
        o[px] = hpack(__ldg(x0 + px), __ldg(x1 + px));
    }
}

// ================= kernel 1: offset conv via mma.sync fp16 2-split (R15 exact) =================
#define OFFB_THREADS 256
#define ST_CH  292
#define ST_ROW 72
#define STRIP_F (16 * ST_CH)
__global__ __launch_bounds__(OFFB_THREADS, 3)
void offset_conv_f16(const float* __restrict__ x,
                     const float* __restrict__ b_off) {
    __shared__ __align__(16) float strip[2][STRIP_F];

    const int h2 = blockIdx.x;
    const int n  = blockIdx.y;
    const int b  = n >> 3, d = n & 7;
    const int tid  = threadIdx.x;
    const int w    = tid >> 5;
    const int lane = tid & 31;
    const int g    = lane >> 2;
    const int t    = lane & 3;
    const int rowsel  = w >> 2;
    const int winbase = (w & 3) * 16;

    float acc[9][4];
#pragma unroll
    for (int nt = 0; nt < 9; nt++)
#pragma unroll
        for (int i = 0; i < 4; i++) acc[nt][i] = 0.f;

    const float* xn = x + (((size_t)b * C_IN) * 8 + d) * HW;

    for (int i = tid; i < 2 * STRIP_F; i += OFFB_THREADS)
        (&strip[0][0])[i] = 0.f;
    __syncthreads();

    auto loadStrip = [&](int buf, int chunk) {
#pragma unroll
        for (int j = 0; j < 4; j++) {
            int f4i = tid + OFFB_THREADS * j;
            int ch  = f4i >> 6;
            int rem = f4i & 63;
            int r   = rem >> 4;
            int q   = rem & 15;
            int hin = h2 * 2 - 1 + r;
            if (hin >= 0 && hin < HH_) {
                float4 v = __ldg(reinterpret_cast<const float4*>(
                    xn + (size_t)(chunk * 16 + ch) * (8 * HW) + hin * WW_ + 4 * q));
                *reinterpret_cast<float4*>(&strip[buf][ch * ST_CH + r * ST_ROW + 4 + 4 * q]) = v;
            }
        }
    };

    loadStrip(0, 0);
    __syncthreads();

    for (int chunk = 0; chunk < 8; chunk++) {
        const int cur = chunk & 1;
        if (chunk < 7) loadStrip(cur ^ 1, chunk + 1);
        const float* S = strip[cur];
        const uint2* Bf = g_wBf + (size_t)chunk * (9 * 9 * 32) + lane;

#pragma unroll
        for (int s = 0; s < 9; s++) {
            const int ky = s / 3, kx = s - 3 * (s / 3);
            const int row  = rowsel + ky;
            const int colb = 3 + winbase + kx;
            const int b0i = (2 * t) * ST_CH + row * ST_ROW + colb;
            float v00 = S[b0i + g],                 v01 = S[b0i + ST_CH + g];
            float v10 = S[b0i + g + 8],             v11 = S[b0i + ST_CH + g + 8];
            float v20 = S[b0i + 8 * ST_CH + g],     v21 = S[b0i + 9 * ST_CH + g];
            float v30 = S[b0i + 8 * ST_CH + g + 8], v31 = S[b0i + 9 * ST_CH + g + 8];
            uint32_t ah[4], al[4];
            hsplit(v00, v01, ah[0], al[0]);
            hsplit(v10, v11, ah[1], al[1]);
            hsplit(v20, v21, ah[2], al[2]);
            hsplit(v30, v31, ah[3], al[3]);
#pragma unroll
            for (int nt = 0; nt < 9; nt++) {
                uint2 bf = __ldg(Bf + (s * 9 + nt) * 32);
                mma_f16(acc[nt], ah, bf.x, bf.y);   // hi*hi
                mma_f16(acc[nt], al, bf.x, bf.y);   // lo*hi
            }
        }
        __syncthreads();
    }

    const int imgrow = h2 * 2 + rowsel;
    float* outp = g_offset + (size_t)n * (OC_OFF * HW) + imgrow * WW_ + winbase;
#pragma unroll
    for (int nt = 0; nt < 9; nt++) {
        int oc0 = nt * 8 + 2 * t;
        float bb0 = __ldg(b_off + oc0), bb1 = __ldg(b_off + oc0 + 1);
        outp[(size_t)oc0       * HW + g    ] = acc[nt][0] + bb0;
        outp[(size_t)(oc0 + 1) * HW + g    ] = acc[nt][1] + bb1;
        outp[(size_t)oc0       * HW + g + 8] = acc[nt][2] + bb0;
        outp[(size_t)(oc0 + 1) * HW + g + 8] = acc[nt][3] + bb1;
    }
}

// ================= kernel 2: deformable conv — fp16 A (no split) + fp16 B 2-split =================
// Samples rounded to fp16 (source data already fp16) -> single-A GEMM:
// 16 MMAs/tap (was 24), half the STS, no lo registers. DF_ROW=20 (bank-clean).
#define DF_ROW 20    // u32 row stride per pixel: hi[16] @0, 4 pad
__global__ __launch_bounds__(128)
void deform_kernel(const float* __restrict__ b_dc) {
    __shared__ __align__(16) uint32_t samp[128 * DF_ROW];   // 10.2 KB
    __shared__ float offs[2 * KK][128];                     // 9 KB

    const int h2 = blockIdx.x;
    const int g  = blockIdx.y;
    const int n  = blockIdx.z;
    const int tid = threadIdx.x;
    const int w    = tid >> 5;
    const int lane = tid & 31;
    const int gl   = lane >> 2;
    const int t    = lane & 3;

    const int sp = tid;
    const int sh = h2 * 2 + (sp >> 6);
    const int sw = sp & 63;
    const uint32_t* xh  = g_xh + ((size_t)(n * 64 + g * 16)) * HW;
    const float*   offb = g_offset + (size_t)n * (OC_OFF * HW)
                        + (size_t)(g * KK * 2) * HW + sh * WW_ + sw;

#pragma unroll
    for (int k = 0; k < 2 * KK; k++)
        offs[k][sp] = __ldg(offb + (size_t)k * HW);
    __syncthreads();

    float acc[2][4][4];
#pragma unroll
    for (int mt = 0; mt < 2; mt++)
#pragma unroll
        for (int nt = 0; nt < 4; nt++)
#pragma unroll
            for (int i = 0; i < 4; i++) acc[mt][nt][i] = 0.f;

    uint32_t* myrow = &samp[sp * DF_ROW];

#pragma unroll 1
    for (int k = 0; k < KK; k++) {
        int ky = k / 3, kx = k - 3 * (k / 3);
        float py = offs[2 * k][sp]     + (float)(sh + ky - 1);
        float px = offs[2 * k + 1][sp] + (float)(sw + kx - 1);
        float y0f = floorf(py), x0f = floorf(px);
        int   y0 = (int)y0f,   x0 = (int)x0f;
        float ly = py - y0f, lx = px - x0f;
        float hy = 1.f - ly, hx = 1.f - lx;
        bool vy0 = (y0 >= 0)  && (y0 < HH_);
        bool vy1 = (y0 >= -1) && (y0 < HH_ - 1);
        bool vx0 = (x0 >= 0)  && (x0 < WW_);
        bool vx1 = (x0 >= -1) && (x0 < WW_ - 1);
        int yc0 = min(max(y0, 0), HH_ - 1), yc1 = min(max(y0 + 1, 0), HH_ - 1);
        int xc0 = min(max(x0, 0), WW_ - 1), xc1 = min(max(x0 + 1, 0), WW_ - 1);
        float w00 = hy * hx * (float)(vy0 && vx0);
        float w01 = hy * lx * (float)(vy0 && vx1);
        float w10 = ly * hx * (float)(vy1 && vx0);
        float w11 = ly * lx * (float)(vy1 && vx1);
        int i00 = yc0 * WW_ + xc0, i01 = yc0 * WW_ + xc1;
        int i10 = yc1 * WW_ + xc0, i11 = yc1 * WW_ + xc1;

        uint32_t hi[16];
#pragma unroll
        for (int cp = 0; cp < 16; cp++) {
            const uint32_t* xc = xh + (size_t)cp * HW;
            uint32_t q00 = __ldg(xc + i00);
            uint32_t q01 = __ldg(xc + i01);
            uint32_t q10 = __ldg(xc + i10);
            uint32_t q11 = __ldg(xc + i11);
            float a0, a1, b0, b1, c0, c1, d0, d1;
            h2f(q00, a0, a1);
            h2f(q01, b0, b1);
            h2f(q10, c0, c1);
            h2f(q11, d0, d1);
            float v0 = fmaf(w00, a0, fmaf(w01, b0, fmaf(w10, c0, w11 * d0)));
            float v1 = fmaf(w00, a1, fmaf(w01, b1, fmaf(w10, c1, w11 * d1)));
            hi[cp] = hpack(v0, v1);
        }
        reinterpret_cast<uint4*>(myrow)[0] = make_uint4(hi[0], hi[1], hi[2], hi[3]);
        reinterpret_cast<uint4*>(myrow)[1] = make_uint4(hi[4], hi[5], hi[6], hi[7]);
        reinterpret_cast<uint4*>(myrow)[2] = make_uint4(hi[8], hi[9], hi[10], hi[11]);
        reinterpret_cast<uint4*>(myrow)[3] = make_uint4(hi[12], hi[13], hi[14], hi[15]);
        __syncwarp();

#pragma unroll
        for (int ks = 0; ks < 2; ks++) {
            uint32_t ah[2][4];
#pragma unroll
            for (int mt = 0; mt < 2; mt++) {
                int r0 = (w * 32 + mt * 16 + gl) * DF_ROW + ks * 8;
                int r1 = r0 + 8 * DF_ROW;
                ah[mt][0] = samp[r0 + t];
                ah[mt][1] = samp[r1 + t];
                ah[mt][2] = samp[r0 + t + 4];
                ah[mt][3] = samp[r1 + t + 4];
            }
            const uint4* Bp = g_wDf + (((size_t)(g * 9 + k) * 2 + ks) * 4) * 32 + lane;
#pragma unroll
            for (int nt = 0; nt < 4; nt++) {
                uint4 bf = __ldg(Bp + nt * 32);
#pragma unroll
                for (int mt = 0; mt < 2; mt++) {
                    mma_f16(acc[mt][nt], ah[mt], bf.x, bf.y);   // A * Bhi
                    mma_f16(acc[mt][nt], ah[mt], bf.z, bf.w);   // A * Blo
                }
            }
        }
        __syncwarp();
    }

    float* outp = g_tmp + ((size_t)n * OUT_C + g * CG) * HW + h2 * 128;
#pragma unroll
    for (int mt = 0; mt < 2; mt++) {
        int px0 = w * 32 + mt * 16 + gl;
#pragma unroll
        for (int nt = 0; nt < 4; nt++) {
            int oc0 = nt * 8 + 2 * t;
            float bb0 = __ldg(b_dc + g * CG + oc0);
            float bb1 = __ldg(b_dc + g * CG + oc0 + 1);
            outp[(size_t)oc0       * HW + px0    ] = acc[mt][nt][0] + bb0;
            outp[(size_t)(oc0 + 1) * HW + px0    ] = acc[mt][nt][1] + bb1;
            outp[(size_t)oc0       * HW + px0 + 8] = acc[mt][nt][2] + bb0;
            outp[(size_t)(oc0 + 1) * HW + px0 + 8] = acc[mt][nt][3] + bb1;
        }
    }
}

// ================= kernel 3: instance norm + GELU + transpose =================
__global__ __launch_bounds__(256)
void finalize_kernel(float* __restrict__ out) {
    const int c = blockIdx.x;
    const int n = blockIdx.y;
    const int b = n >> 3, d = n & 7;
    const int tid = threadIdx.x;

    const float* tp = g_tmp + ((size_t)n * OUT_C + c) * HW;
    float v[16];
    float s = 0.f, ss = 0.f;
#pragma unroll
    for (int i = 0; i < 16; i++) {
        float t = tp[tid + 256 * i];
        v[i] = t; s += t; ss += t * t;
    }
#pragma unroll
    for (int o = 16; o > 0; o >>= 1) {
        s  += __shfl_down_sync(0xffffffffu, s,  o);
        ss += __shfl_down_sync(0xffffffffu, ss, o);
    }
    __shared__ float s1[8], s2[8];
    __shared__ float mu_s, inv_s;
    int wid = tid >> 5, lane = tid & 31;
    if (lane == 0) { s1[wid] = s; s2[wid] = ss; }
    __syncthreads();
    if (tid == 0) {
        float ts = 0.f, tss = 0.f;
#pragma unroll
        for (int i = 0; i < 8; i++) { ts += s1[i]; tss += s2[i]; }
        float mu  = ts * (1.f / 4096.f);
        float var = tss * (1.f / 4096.f) - mu * mu;
        mu_s  = mu;
        inv_s = rsqrtf(var + 1e-5f);
    }
    __syncthreads();
    float mu = mu_s, inv = inv_s;

    float* op = out + (((size_t)b * OUT_C + c) * 8 + d) * HW;
#pragma unroll
    for (int i = 0; i < 16; i++) {
        float t = (v[i] - mu) * inv;
        op[tid + 256 * i] = 0.5f * t * (1.f + erff(t * 0.70710678118654752f));
    }
}

// ================= launcher: monolithic serial chain =================
extern "C" void kernel_launch(void* const* d_in, const int* in_sizes, int n_in,
                              void* d_out, int out_size) {
    (void)in_sizes; (void)n_in; (void)out_size;
    const float* x     = (const float*)d_in[0];
    const float* w_off = (const float*)d_in[1];
    const float* b_off = (const float*)d_in[2];
    const float* w_dc  = (const float*)d_in[3];
    const float* b_dc  = (const float*)d_in[4];
    float* out = (float*)d_out;

    prep_kernel<<<(8 * 9 * 9 * 32 + 255) / 256, 256>>>(w_off, w_dc);

    dim3 gxh(64, NB);
    xhalf_kernel<<<gxh, 256>>>(x);

    dim3 gco(32, NB);
    offset_conv_f16<<<gco, OFFB_THREADS>>>(x, b_off);

    dim3 gdf(32, OG, NB);
    deform_kernel<<<gdf, 128>>>(b_dc);

    dim3 gfn(OUT_C, NB);
    finalize_kernel<<<gfn, 256>>>(out);
}